// round 15
// baseline (speedup 1.0000x reference)
#include <cuda_runtime.h>
#include <math.h>
#include <stdint.h>

#define N_NODES 100000
#define N_EDGES 3200000
#define IN_CH   602
#define HID     16
#define OUT_CH  41

#define M_TILE   256
#define KC       16
#define XS_ROW   (KC + 4)                  // 20 floats: conflict-free phases, 16B-aligned rows
#define NCH      ((IN_CH + KC - 1) / KC)   // 38
#define SCAN_BLK 1024
#define NB_SCAN  ((N_NODES + SCAN_BLK - 1) / SCAN_BLK)   // 98

// packed f32x2 FMA: acc = a*b + acc  (per-lane IEEE fp32)
#define FMA2(acc, a, b) \
    asm volatile("fma.rn.f32x2 %0, %1, %2, %0;" : "+l"(acc) : "l"(a), "l"(b))

// Scratch (device globals; no allocation allowed)
__device__ float g_h1   [N_NODES * HID];
__device__ float g_r    [N_NODES * HID];
__device__ int   g_deg  [N_NODES];
__device__ int   g_excl [N_NODES];
__device__ int   g_blksum[128];
__device__ int   g_rowptr[N_NODES + 1];
__device__ int   g_cursor[N_NODES];
__device__ int   g_csr  [N_EDGES];

// ---------------------------------------------------------------------------
// Chunk loader: 16 consecutive k of one row into 4 float4 regs.
// evenrow: row base 16B-aligned -> 4x LDG.128.
// oddrow:  row base 8B-aligned  -> LDG.64 + 3x LDG.128 (at k+2) + LDG.64.
// Guards are warp-uniform (only the tail chunk takes scalar fallbacks).
// ---------------------------------------------------------------------------
__device__ __forceinline__ void load_chunk(const float* __restrict__ xrow,
                                           int kc, bool evenrow, float4 pf[4]) {
    if (evenrow) {
        #pragma unroll
        for (int q = 0; q < 4; q++) {
            int gk = kc + q * 4;
            float4 v = make_float4(0.f, 0.f, 0.f, 0.f);
            if (gk + 3 < IN_CH) {
                v = *(const float4*)(xrow + gk);
            } else {
                if (gk     < IN_CH) v.x = xrow[gk];
                if (gk + 1 < IN_CH) v.y = xrow[gk + 1];
                if (gk + 2 < IN_CH) v.z = xrow[gk + 2];
                if (gk + 3 < IN_CH) v.w = xrow[gk + 3];
            }
            pf[q] = v;
        }
    } else {
        float2 h = make_float2(0.f, 0.f), t = make_float2(0.f, 0.f);
        float4 A = make_float4(0.f, 0.f, 0.f, 0.f), B = A, C = A;
        if (kc + 1 < IN_CH) h = *(const float2*)(xrow + kc);
        if (kc + 5 < IN_CH) A = *(const float4*)(xrow + kc + 2);
        else {
            if (kc + 2 < IN_CH) A.x = xrow[kc + 2];
            if (kc + 3 < IN_CH) A.y = xrow[kc + 3];
            if (kc + 4 < IN_CH) A.z = xrow[kc + 4];
        }
        if (kc + 9 < IN_CH) B = *(const float4*)(xrow + kc + 6);
        else {
            if (kc + 6 < IN_CH) B.x = xrow[kc + 6];
            if (kc + 7 < IN_CH) B.y = xrow[kc + 7];
            if (kc + 8 < IN_CH) B.z = xrow[kc + 8];
        }
        if (kc + 13 < IN_CH) C = *(const float4*)(xrow + kc + 10);
        else {
            if (kc + 10 < IN_CH) C.x = xrow[kc + 10];
            if (kc + 11 < IN_CH) C.y = xrow[kc + 11];
            if (kc + 12 < IN_CH) C.z = xrow[kc + 12];
        }
        if (kc + 15 < IN_CH) t = *(const float2*)(xrow + kc + 14);
        else if (kc + 14 < IN_CH) t.x = xrow[kc + 14];
        pf[0] = make_float4(h.x, h.y, A.x, A.y);
        pf[1] = make_float4(A.z, A.w, B.x, B.y);
        pf[2] = make_float4(B.z, B.w, C.x, C.y);
        pf[3] = make_float4(C.z, C.w, t.x, t.y);
    }
}

// ---------------------------------------------------------------------------
// K1: h1[N,16] = x[N,602] @ W1[602,16].
// Parity-segregated rows (warps 0-3 even, 4-7 odd) -> wide LDG, no divergence.
// FMA2 packed inner loop (proven round-14).  Double-buffered reg prefetch.
// ---------------------------------------------------------------------------
__global__ __launch_bounds__(256)
void gemm1_kernel(const float* __restrict__ x,
                  const float* __restrict__ W1,
                  float* __restrict__ h1) {
    __shared__ float xs[M_TILE][XS_ROW];
    __shared__ __align__(16) float ws[KC][HID];

    const int tid      = threadIdx.x;
    const int row_base = blockIdx.x * M_TILE;
    const bool evenrow = (tid < 128);
    const int srow = evenrow ? (2 * tid) : (2 * (tid - 128) + 1);  // tile row

    const int wk = tid >> 4;         // W: k row 0..15
    const int wc = tid & 15;         // W: col

    int grow = row_base + srow;
    // clamp to a row of MATCHING PARITY so alignment invariants hold
    int cr = (grow < N_NODES) ? grow : (evenrow ? 0 : 1);
    const float* xrow = x + (size_t)cr * IN_CH;

    float4 pf[4];
    float  pw;

    uint64_t accp[8];                // 8 packed f32x2 accumulators = 16 cols
    #pragma unroll
    for (int j = 0; j < 8; j++) accp[j] = 0ull;

    // ---- prefetch chunk 0 ----
    load_chunk(xrow, 0, evenrow, pf);
    pw = (wk < IN_CH) ? W1[(size_t)wk * HID + wc] : 0.f;

    #pragma unroll 1
    for (int c = 0; c < NCH; c++) {
        // store staged chunk: 4x STS.128 (8-lane phases conflict-free)
        *(float4*)&xs[tid][0]  = pf[0];
        *(float4*)&xs[tid][4]  = pf[1];
        *(float4*)&xs[tid][8]  = pf[2];
        *(float4*)&xs[tid][12] = pf[3];
        ws[wk][wc] = pw;
        __syncthreads();

        // prefetch chunk c+1 (LDGs overlap the compute below)
        if (c + 1 < NCH) {
            const int kc = (c + 1) * KC;
            load_chunk(xrow, kc, evenrow, pf);
            pw = (kc + wk < IN_CH) ? W1[(size_t)(kc + wk) * HID + wc] : 0.f;
        }

        // compute current chunk: LDS.128 of own row + packed FMA2
        #pragma unroll
        for (int k0 = 0; k0 < KC; k0 += 4) {
            float4 xv = *(const float4*)&xs[tid][k0];
            #pragma unroll
            for (int kk = 0; kk < 4; kk++) {
                float xk = (kk == 0) ? xv.x : (kk == 1) ? xv.y
                         : (kk == 2) ? xv.z : xv.w;
                uint64_t xk2;
                asm("mov.b64 %0, {%1, %1};" : "=l"(xk2) : "f"(xk));
                ulonglong2 wA = *(const ulonglong2*)&ws[k0 + kk][0];
                ulonglong2 wB = *(const ulonglong2*)&ws[k0 + kk][4];
                ulonglong2 wC = *(const ulonglong2*)&ws[k0 + kk][8];
                ulonglong2 wD = *(const ulonglong2*)&ws[k0 + kk][12];
                FMA2(accp[0], xk2, wA.x);  FMA2(accp[1], xk2, wA.y);
                FMA2(accp[2], xk2, wB.x);  FMA2(accp[3], xk2, wB.y);
                FMA2(accp[4], xk2, wC.x);  FMA2(accp[5], xk2, wC.y);
                FMA2(accp[6], xk2, wD.x);  FMA2(accp[7], xk2, wD.y);
            }
        }
        __syncthreads();
    }

    if (grow < N_NODES) {
        float* op = h1 + (size_t)grow * 16;
        #pragma unroll
        for (int q = 0; q < 4; q++) {
            float a, b, cc, d;
            asm("mov.b64 {%0, %1}, %2;" : "=f"(a), "=f"(b) : "l"(accp[q*2]));
            asm("mov.b64 {%0, %1}, %2;" : "=f"(cc), "=f"(d) : "l"(accp[q*2+1]));
            *(float4*)(op + q * 4) = make_float4(a, b, cc, d);
        }
    }
}

// ---------------------------------------------------------------------------
// CSR construction  (proven path)
// ---------------------------------------------------------------------------
__global__ void deg_kernel(const int* __restrict__ dst, int* __restrict__ deg) {
    int e = blockIdx.x * blockDim.x + threadIdx.x;
    if (e < N_EDGES) atomicAdd(&deg[dst[e]], 1);
}

__global__ __launch_bounds__(SCAN_BLK)
void scan1_kernel(const int* __restrict__ deg,
                  int* __restrict__ excl,
                  int* __restrict__ blksum) {
    __shared__ int wsum[32];
    int tid = threadIdx.x, lane = tid & 31, wid = tid >> 5;
    int i = blockIdx.x * SCAN_BLK + tid;
    int v = (i < N_NODES) ? deg[i] : 0;
    int x = v;
    #pragma unroll
    for (int d = 1; d < 32; d <<= 1) {
        int t = __shfl_up_sync(0xffffffffu, x, d);
        if (lane >= d) x += t;
    }
    if (lane == 31) wsum[wid] = x;
    __syncthreads();
    if (wid == 0) {
        int s = wsum[lane];
        #pragma unroll
        for (int d = 1; d < 32; d <<= 1) {
            int t = __shfl_up_sync(0xffffffffu, s, d);
            if (lane >= d) s += t;
        }
        wsum[lane] = s;
    }
    __syncthreads();
    int woff = (wid == 0) ? 0 : wsum[wid - 1];
    if (i < N_NODES) excl[i] = woff + x - v;
    if (tid == SCAN_BLK - 1) blksum[blockIdx.x] = wsum[31];
}

__global__ __launch_bounds__(128)
void scan2_kernel(int* __restrict__ blksum) {
    __shared__ int ws[4];
    int tid = threadIdx.x, lane = tid & 31, wid = tid >> 5;
    int v = (tid < NB_SCAN) ? blksum[tid] : 0;
    int x = v;
    #pragma unroll
    for (int d = 1; d < 32; d <<= 1) {
        int t = __shfl_up_sync(0xffffffffu, x, d);
        if (lane >= d) x += t;
    }
    if (lane == 31) ws[wid] = x;
    __syncthreads();
    int woff = 0;
    #pragma unroll
    for (int w = 0; w < 4; w++) if (w < wid) woff += ws[w];
    if (tid < NB_SCAN) blksum[tid] = woff + x - v;
}

__global__ void scan3_kernel(const int* __restrict__ excl,
                             const int* __restrict__ blksum,
                             int* __restrict__ rowptr,
                             int* __restrict__ cursor) {
    int i = blockIdx.x * blockDim.x + threadIdx.x;
    if (i >= N_NODES) return;
    int v = excl[i] + blksum[i / SCAN_BLK];
    rowptr[i] = v;
    cursor[i] = v;
    if (i == 0) rowptr[N_NODES] = N_EDGES;
}

__global__ void fill_kernel(const int* __restrict__ src,
                            const int* __restrict__ dst,
                            int* __restrict__ cursor,
                            int* __restrict__ csr_src) {
    int e = blockIdx.x * blockDim.x + threadIdx.x;
    if (e >= N_EDGES) return;
    int slot = atomicAdd(&cursor[dst[e]], 1);
    csr_src[slot] = src[e];
}

// ---------------------------------------------------------------------------
// Gather layer 1: 4 threads per node, float4 loads, csr indices deduped via
// group-masked width-4 shuffles.  (proven round-13 version)
// ---------------------------------------------------------------------------
__global__ void gather1_kernel(const float* __restrict__ h,
                               const int* __restrict__ rowptr,
                               const int* __restrict__ csr_src,
                               const float* __restrict__ bias,
                               float* __restrict__ out) {
    int t = blockIdx.x * blockDim.x + threadIdx.x;
    int nid = t >> 2;
    int c4  = t & 3;
    unsigned gmask = 0xFu << ((threadIdx.x & 31) & ~3);   // this 4-lane group
    if (nid >= N_NODES) return;
    int beg = rowptr[nid];
    int end = rowptr[nid + 1];
    const float4* hv = (const float4*)h;
    float4 s = make_float4(0.f, 0.f, 0.f, 0.f);
    int j = beg;
    for (; j + 4 <= end; j += 4) {
        int myi = csr_src[j + c4];
        int s0 = __shfl_sync(gmask, myi, 0, 4);
        int s1 = __shfl_sync(gmask, myi, 1, 4);
        int s2 = __shfl_sync(gmask, myi, 2, 4);
        int s3 = __shfl_sync(gmask, myi, 3, 4);
        float4 v0 = hv[(size_t)s0 * 4 + c4];
        float4 v1 = hv[(size_t)s1 * 4 + c4];
        float4 v2 = hv[(size_t)s2 * 4 + c4];
        float4 v3 = hv[(size_t)s3 * 4 + c4];
        s.x += (v0.x + v1.x) + (v2.x + v3.x);
        s.y += (v0.y + v1.y) + (v2.y + v3.y);
        s.z += (v0.z + v1.z) + (v2.z + v3.z);
        s.w += (v0.w + v1.w) + (v2.w + v3.w);
    }
    for (; j < end; j++) {
        float4 v = hv[(size_t)csr_src[j] * 4 + c4];
        s.x += v.x; s.y += v.y; s.z += v.z; s.w += v.w;
    }
    float inv = 1.f / fmaxf((float)(end - beg), 1.f);
    float4 m;
    m.x = s.x * inv; m.y = s.y * inv; m.z = s.z * inv; m.w = s.w * inv;
    float4 bb = __ldg(((const float4*)bias) + c4);
    m.x = fmaxf(m.x + bb.x, 0.f);
    m.y = fmaxf(m.y + bb.y, 0.f);
    m.z = fmaxf(m.z + bb.z, 0.f);
    m.w = fmaxf(m.w + bb.w, 0.f);
    ((float4*)out)[(size_t)nid * 4 + c4] = m;
}

// ---------------------------------------------------------------------------
// Fused gather2 + W2 matvec + log_softmax.  (proven round-13 version)
// ---------------------------------------------------------------------------
__global__ void gather2_out_kernel(const float* __restrict__ h,
                                   const int* __restrict__ rowptr,
                                   const int* __restrict__ csr_src,
                                   const float* __restrict__ W2,
                                   const float* __restrict__ b2,
                                   float* __restrict__ out) {
    __shared__ float w2s[HID * OUT_CH];
    __shared__ float b2s[OUT_CH];
    for (int i = threadIdx.x; i < HID * OUT_CH; i += blockDim.x) w2s[i] = W2[i];
    for (int i = threadIdx.x; i < OUT_CH;       i += blockDim.x) b2s[i] = b2[i];
    __syncthreads();

    int t = blockIdx.x * blockDim.x + threadIdx.x;
    int nid = t >> 2;
    int c4  = t & 3;
    unsigned gmask = 0xFu << ((threadIdx.x & 31) & ~3);   // this 4-lane group
    if (nid >= N_NODES) return;
    int beg = rowptr[nid];
    int end = rowptr[nid + 1];
    const float4* hv = (const float4*)h;
    float4 s = make_float4(0.f, 0.f, 0.f, 0.f);
    int j = beg;
    for (; j + 4 <= end; j += 4) {
        int myi = csr_src[j + c4];
        int s0 = __shfl_sync(gmask, myi, 0, 4);
        int s1 = __shfl_sync(gmask, myi, 1, 4);
        int s2 = __shfl_sync(gmask, myi, 2, 4);
        int s3 = __shfl_sync(gmask, myi, 3, 4);
        float4 v0 = hv[(size_t)s0 * 4 + c4];
        float4 v1 = hv[(size_t)s1 * 4 + c4];
        float4 v2 = hv[(size_t)s2 * 4 + c4];
        float4 v3 = hv[(size_t)s3 * 4 + c4];
        s.x += (v0.x + v1.x) + (v2.x + v3.x);
        s.y += (v0.y + v1.y) + (v2.y + v3.y);
        s.z += (v0.z + v1.z) + (v2.z + v3.z);
        s.w += (v0.w + v1.w) + (v2.w + v3.w);
    }
    for (; j < end; j++) {
        float4 v = hv[(size_t)csr_src[j] * 4 + c4];
        s.x += v.x; s.y += v.y; s.z += v.z; s.w += v.w;
    }
    float inv = 1.f / fmaxf((float)(end - beg), 1.f);
    float4 m;
    m.x = s.x * inv; m.y = s.y * inv; m.z = s.z * inv; m.w = s.w * inv;

    // share the 16 mean channels across the 4-lane group
    float ma[16];
    #pragma unroll
    for (int sl = 0; sl < 4; sl++) {
        ma[sl * 4 + 0] = __shfl_sync(gmask, m.x, sl, 4);
        ma[sl * 4 + 1] = __shfl_sync(gmask, m.y, sl, 4);
        ma[sl * 4 + 2] = __shfl_sync(gmask, m.z, sl, 4);
        ma[sl * 4 + 3] = __shfl_sync(gmask, m.w, sl, 4);
    }

    // each lane computes logits j = c4 + 4*i  (11 slots; last may be unused)
    float o[11];
    float lmax = -1e30f;
    int cnt = 0;
    for (int jj = c4; jj < OUT_CH; jj += 4, cnt++) {
        float v = b2s[jj];
        #pragma unroll
        for (int k = 0; k < HID; k++)
            v += ma[k] * w2s[k * OUT_CH + jj];
        o[cnt] = v;
        lmax = fmaxf(lmax, v);
    }
    // group reductions (xor 1, 2 stay inside the 4-lane group)
    lmax = fmaxf(lmax, __shfl_xor_sync(gmask, lmax, 1));
    lmax = fmaxf(lmax, __shfl_xor_sync(gmask, lmax, 2));
    float lsum = 0.f;
    for (int i = 0; i < cnt; i++) lsum += __expf(o[i] - lmax);
    lsum += __shfl_xor_sync(gmask, lsum, 1);
    lsum += __shfl_xor_sync(gmask, lsum, 2);
    float ls = __logf(lsum) + lmax;

    float* op = out + (size_t)nid * OUT_CH;
    int i = 0;
    for (int jj = c4; jj < OUT_CH; jj += 4, i++) op[jj] = o[i] - ls;
}

// ---------------------------------------------------------------------------
extern "C" void kernel_launch(void* const* d_in, const int* in_sizes, int n_in,
                              void* d_out, int out_size) {
    const float* x  = (const float*)d_in[0];
    const int*   ei = (const int*)  d_in[1];
    const float* W1 = (const float*)d_in[2];
    const float* b1 = (const float*)d_in[3];
    const float* W2 = (const float*)d_in[4];
    const float* b2 = (const float*)d_in[5];
    float* out = (float*)d_out;

    const int* src = ei;
    const int* dst = ei + N_EDGES;

    float *p_h1, *p_r;
    int *p_deg, *p_excl, *p_blksum, *p_rowptr, *p_cursor, *p_csr;
    cudaGetSymbolAddress((void**)&p_h1,     g_h1);
    cudaGetSymbolAddress((void**)&p_r,      g_r);
    cudaGetSymbolAddress((void**)&p_deg,    g_deg);
    cudaGetSymbolAddress((void**)&p_excl,   g_excl);
    cudaGetSymbolAddress((void**)&p_blksum, g_blksum);
    cudaGetSymbolAddress((void**)&p_rowptr, g_rowptr);
    cudaGetSymbolAddress((void**)&p_cursor, g_cursor);
    cudaGetSymbolAddress((void**)&p_csr,    g_csr);

    // Side stream + fork/join events (created on first call, which is the
    // uncaptured correctness run; reused identically during graph capture).
    static cudaStream_t s_csr = nullptr;
    static cudaEvent_t  ev_fork = nullptr, ev_join = nullptr;
    if (s_csr == nullptr) {
        cudaStreamCreateWithFlags(&s_csr, cudaStreamNonBlocking);
        cudaEventCreateWithFlags(&ev_fork, cudaEventDisableTiming);
        cudaEventCreateWithFlags(&ev_join, cudaEventDisableTiming);
    }

    // Fork: CSR chain on side stream, gemm on main stream — independent.
    cudaEventRecord(ev_fork, 0);
    cudaStreamWaitEvent(s_csr, ev_fork, 0);

    cudaMemsetAsync(p_deg, 0, sizeof(int) * N_NODES, s_csr);
    deg_kernel <<<(N_EDGES + 255) / 256, 256, 0, s_csr>>>(dst, p_deg);
    scan1_kernel<<<NB_SCAN, SCAN_BLK, 0, s_csr>>>(p_deg, p_excl, p_blksum);
    scan2_kernel<<<1, 128, 0, s_csr>>>(p_blksum);
    scan3_kernel<<<(N_NODES + 255) / 256, 256, 0, s_csr>>>(p_excl, p_blksum, p_rowptr, p_cursor);
    fill_kernel <<<(N_EDGES + 255) / 256, 256, 0, s_csr>>>(src, dst, p_cursor, p_csr);
    cudaEventRecord(ev_join, s_csr);

    // K1 on main stream, overlapped with CSR build
    gemm1_kernel<<<(N_NODES + M_TILE - 1) / M_TILE, 256>>>(x, W1, p_h1);

    // Join: gather1 needs both h1 and the CSR
    cudaStreamWaitEvent(0, ev_join, 0);

    gather1_kernel<<<(N_NODES * 4 + 255) / 256, 256>>>(p_h1, p_rowptr, p_csr, b1, p_r);
    gather2_out_kernel<<<(N_NODES * 4 + 255) / 256, 256>>>(p_r, p_rowptr, p_csr, W2, b2, out);
}

// round 16
// speedup vs baseline: 1.1280x; 1.1280x over previous
#include <cuda_runtime.h>
#include <math.h>
#include <stdint.h>

#define N_NODES 100000
#define N_EDGES 3200000
#define IN_CH   602
#define HID     16
#define OUT_CH  41

#define M_TILE   256
#define KC       16
#define XS_ROW   (KC + 4)                  // 20 floats: conflict-free LDS.128, 16B-aligned rows
#define NCH      ((IN_CH + KC - 1) / KC)   // 38
#define SCAN_BLK 1024
#define NB_SCAN  ((N_NODES + SCAN_BLK - 1) / SCAN_BLK)   // 98

// packed f32x2 FMA: acc = a*b + acc  (per-lane IEEE fp32)
#define FMA2(acc, a, b) \
    asm volatile("fma.rn.f32x2 %0, %1, %2, %0;" : "+l"(acc) : "l"(a), "l"(b))

// Scratch (device globals; no allocation allowed)
__device__ float g_h1   [N_NODES * HID];
__device__ float g_r    [N_NODES * HID];
__device__ int   g_deg  [N_NODES];
__device__ int   g_excl [N_NODES];
__device__ int   g_blksum[128];
__device__ int   g_rowptr[N_NODES + 1];
__device__ int   g_cursor[N_NODES];
__device__ int   g_csr  [N_EDGES];

// ---------------------------------------------------------------------------
// K1: h1[N,16] = x[N,602] @ W1[602,16].  (EXACT round-14 proven version)
// ---------------------------------------------------------------------------
__global__ __launch_bounds__(256)
void gemm1_kernel(const float* __restrict__ x,
                  const float* __restrict__ W1,
                  float* __restrict__ h1) {
    __shared__ float xs[M_TILE][XS_ROW];
    __shared__ __align__(16) float ws[KC][HID];

    const int tid      = threadIdx.x;
    const int row_base = blockIdx.x * M_TILE;
    const int rl = tid;              // compute: local row (1 row per thread)

    const int pr = tid >> 3;         // prefetch row lane 0..31
    const int pk = (tid & 7) * 2;    // prefetch k-pair 0,2,...,14
    const int wk = tid >> 4;         // W: k row 0..15
    const int wc = tid & 15;         // W: col

    float2 px[8];
    float  pw;

    uint64_t accp[8];                // 8 packed f32x2 accumulators = 16 cols
    #pragma unroll
    for (int j = 0; j < 8; j++) accp[j] = 0ull;

    // ---- prefetch chunk 0 ----
    {
        const int kc = 0;
        #pragma unroll
        for (int i = 0; i < 8; i++) {
            int r = i * 32 + pr;
            int grow = row_base + r;
            int cr = (grow < N_NODES) ? grow : 0;
            int gk = kc + pk;
            float2 v = make_float2(0.f, 0.f);
            if (gk + 1 < IN_CH) v = *(const float2*)(x + (size_t)cr * IN_CH + gk);
            px[i] = v;
        }
        pw = (wk < IN_CH) ? W1[(size_t)wk * HID + wc] : 0.f;
    }

    #pragma unroll 1
    for (int c = 0; c < NCH; c++) {
        #pragma unroll
        for (int i = 0; i < 8; i++) {
            *(float2*)&xs[i * 32 + pr][pk] = px[i];
        }
        ws[wk][wc] = pw;
        __syncthreads();

        if (c + 1 < NCH) {
            const int kc = (c + 1) * KC;
            #pragma unroll
            for (int i = 0; i < 8; i++) {
                int r = i * 32 + pr;
                int grow = row_base + r;
                int cr = (grow < N_NODES) ? grow : 0;
                int gk = kc + pk;
                float2 v = make_float2(0.f, 0.f);
                if (gk + 1 < IN_CH) v = *(const float2*)(x + (size_t)cr * IN_CH + gk);
                px[i] = v;
            }
            pw = (kc + wk < IN_CH) ? W1[(size_t)(kc + wk) * HID + wc] : 0.f;
        }

        #pragma unroll
        for (int k0 = 0; k0 < KC; k0 += 4) {
            float4 xv = *(const float4*)&xs[rl][k0];
            #pragma unroll
            for (int kk = 0; kk < 4; kk++) {
                float xk = (kk == 0) ? xv.x : (kk == 1) ? xv.y
                         : (kk == 2) ? xv.z : xv.w;
                uint64_t xk2;
                asm("mov.b64 %0, {%1, %1};" : "=l"(xk2) : "f"(xk));
                ulonglong2 wA = *(const ulonglong2*)&ws[k0 + kk][0];
                ulonglong2 wB = *(const ulonglong2*)&ws[k0 + kk][4];
                ulonglong2 wC = *(const ulonglong2*)&ws[k0 + kk][8];
                ulonglong2 wD = *(const ulonglong2*)&ws[k0 + kk][12];
                FMA2(accp[0], xk2, wA.x);  FMA2(accp[1], xk2, wA.y);
                FMA2(accp[2], xk2, wB.x);  FMA2(accp[3], xk2, wB.y);
                FMA2(accp[4], xk2, wC.x);  FMA2(accp[5], xk2, wC.y);
                FMA2(accp[6], xk2, wD.x);  FMA2(accp[7], xk2, wD.y);
            }
        }
        __syncthreads();
    }

    int row = row_base + rl;
    if (row < N_NODES) {
        float* op = h1 + (size_t)row * 16;
        #pragma unroll
        for (int q = 0; q < 4; q++) {
            float a, b, cc, d;
            asm("mov.b64 {%0, %1}, %2;" : "=f"(a), "=f"(b) : "l"(accp[q*2]));
            asm("mov.b64 {%0, %1}, %2;" : "=f"(cc), "=f"(d) : "l"(accp[q*2+1]));
            *(float4*)(op + q * 4) = make_float4(a, b, cc, d);
        }
    }
}

// ---------------------------------------------------------------------------
// CSR construction  (proven path)
// ---------------------------------------------------------------------------
__global__ void deg_kernel(const int* __restrict__ dst, int* __restrict__ deg) {
    int e = blockIdx.x * blockDim.x + threadIdx.x;
    if (e < N_EDGES) atomicAdd(&deg[dst[e]], 1);
}

__global__ __launch_bounds__(SCAN_BLK)
void scan1_kernel(const int* __restrict__ deg,
                  int* __restrict__ excl,
                  int* __restrict__ blksum) {
    __shared__ int wsum[32];
    int tid = threadIdx.x, lane = tid & 31, wid = tid >> 5;
    int i = blockIdx.x * SCAN_BLK + tid;
    int v = (i < N_NODES) ? deg[i] : 0;
    int x = v;
    #pragma unroll
    for (int d = 1; d < 32; d <<= 1) {
        int t = __shfl_up_sync(0xffffffffu, x, d);
        if (lane >= d) x += t;
    }
    if (lane == 31) wsum[wid] = x;
    __syncthreads();
    if (wid == 0) {
        int s = wsum[lane];
        #pragma unroll
        for (int d = 1; d < 32; d <<= 1) {
            int t = __shfl_up_sync(0xffffffffu, s, d);
            if (lane >= d) s += t;
        }
        wsum[lane] = s;
    }
    __syncthreads();
    int woff = (wid == 0) ? 0 : wsum[wid - 1];
    if (i < N_NODES) excl[i] = woff + x - v;
    if (tid == SCAN_BLK - 1) blksum[blockIdx.x] = wsum[31];
}

__global__ __launch_bounds__(128)
void scan2_kernel(int* __restrict__ blksum) {
    __shared__ int ws[4];
    int tid = threadIdx.x, lane = tid & 31, wid = tid >> 5;
    int v = (tid < NB_SCAN) ? blksum[tid] : 0;
    int x = v;
    #pragma unroll
    for (int d = 1; d < 32; d <<= 1) {
        int t = __shfl_up_sync(0xffffffffu, x, d);
        if (lane >= d) x += t;
    }
    if (lane == 31) ws[wid] = x;
    __syncthreads();
    int woff = 0;
    #pragma unroll
    for (int w = 0; w < 4; w++) if (w < wid) woff += ws[w];
    if (tid < NB_SCAN) blksum[tid] = woff + x - v;
}

__global__ void scan3_kernel(const int* __restrict__ excl,
                             const int* __restrict__ blksum,
                             int* __restrict__ rowptr,
                             int* __restrict__ cursor) {
    int i = blockIdx.x * blockDim.x + threadIdx.x;
    if (i >= N_NODES) return;
    int v = excl[i] + blksum[i / SCAN_BLK];
    rowptr[i] = v;
    cursor[i] = v;
    if (i == 0) rowptr[N_NODES] = N_EDGES;
}

__global__ void fill_kernel(const int* __restrict__ src,
                            const int* __restrict__ dst,
                            int* __restrict__ cursor,
                            int* __restrict__ csr_src) {
    int e = blockIdx.x * blockDim.x + threadIdx.x;
    if (e >= N_EDGES) return;
    int slot = atomicAdd(&cursor[dst[e]], 1);
    csr_src[slot] = src[e];
}

// ---------------------------------------------------------------------------
// Shared gather body: 4 threads/node; tiered edge loop (peel-to-even, 8-edge
// int2 batches, 4-edge batch, singles).  Group-uniform trip counts.
// ---------------------------------------------------------------------------
__device__ __forceinline__ float4 gather_mean(const float4* __restrict__ hv,
                                              const int* __restrict__ csr_src,
                                              int beg, int end, int c4,
                                              unsigned gmask) {
    float4 s = make_float4(0.f, 0.f, 0.f, 0.f);
    int j = beg;
    // peel to even j (int2 alignment)
    if ((j & 1) && j < end) {
        float4 v = hv[(size_t)csr_src[j] * 4 + c4];
        s.x += v.x; s.y += v.y; s.z += v.z; s.w += v.w;
        j++;
    }
    // 8-edge batches: lane c4 loads 2 indices as int2
    for (; j + 8 <= end; j += 8) {
        int2 myi = *(const int2*)(csr_src + j + 2 * c4);
        #pragma unroll
        for (int q = 0; q < 4; q++) {
            int ia = __shfl_sync(gmask, myi.x, q, 4);
            int ib = __shfl_sync(gmask, myi.y, q, 4);
            float4 va = hv[(size_t)ia * 4 + c4];
            float4 vb = hv[(size_t)ib * 4 + c4];
            s.x += va.x + vb.x;
            s.y += va.y + vb.y;
            s.z += va.z + vb.z;
            s.w += va.w + vb.w;
        }
    }
    // 4-edge batch
    if (j + 4 <= end) {
        int myi = csr_src[j + c4];
        int s0 = __shfl_sync(gmask, myi, 0, 4);
        int s1 = __shfl_sync(gmask, myi, 1, 4);
        int s2 = __shfl_sync(gmask, myi, 2, 4);
        int s3 = __shfl_sync(gmask, myi, 3, 4);
        float4 v0 = hv[(size_t)s0 * 4 + c4];
        float4 v1 = hv[(size_t)s1 * 4 + c4];
        float4 v2 = hv[(size_t)s2 * 4 + c4];
        float4 v3 = hv[(size_t)s3 * 4 + c4];
        s.x += (v0.x + v1.x) + (v2.x + v3.x);
        s.y += (v0.y + v1.y) + (v2.y + v3.y);
        s.z += (v0.z + v1.z) + (v2.z + v3.z);
        s.w += (v0.w + v1.w) + (v2.w + v3.w);
        j += 4;
    }
    // singles
    for (; j < end; j++) {
        float4 v = hv[(size_t)csr_src[j] * 4 + c4];
        s.x += v.x; s.y += v.y; s.z += v.z; s.w += v.w;
    }
    float inv = 1.f / fmaxf((float)(end - beg), 1.f);
    return make_float4(s.x * inv, s.y * inv, s.z * inv, s.w * inv);
}

// ---------------------------------------------------------------------------
// Gather layer 1: r = relu(mean_nbr(h1) + b1).
// ---------------------------------------------------------------------------
__global__ void gather1_kernel(const float* __restrict__ h,
                               const int* __restrict__ rowptr,
                               const int* __restrict__ csr_src,
                               const float* __restrict__ bias,
                               float* __restrict__ out) {
    int t = blockIdx.x * blockDim.x + threadIdx.x;
    int nid = t >> 2;
    int c4  = t & 3;
    unsigned gmask = 0xFu << ((threadIdx.x & 31) & ~3);
    if (nid >= N_NODES) return;
    int beg = rowptr[nid];
    int end = rowptr[nid + 1];
    float4 m = gather_mean((const float4*)h, csr_src, beg, end, c4, gmask);
    float4 bb = __ldg(((const float4*)bias) + c4);
    m.x = fmaxf(m.x + bb.x, 0.f);
    m.y = fmaxf(m.y + bb.y, 0.f);
    m.z = fmaxf(m.z + bb.z, 0.f);
    m.w = fmaxf(m.w + bb.w, 0.f);
    ((float4*)out)[(size_t)nid * 4 + c4] = m;
}

// ---------------------------------------------------------------------------
// Fused gather2 + W2 matvec + log_softmax.  (round-13 epilogue)
// ---------------------------------------------------------------------------
__global__ void gather2_out_kernel(const float* __restrict__ h,
                                   const int* __restrict__ rowptr,
                                   const int* __restrict__ csr_src,
                                   const float* __restrict__ W2,
                                   const float* __restrict__ b2,
                                   float* __restrict__ out) {
    __shared__ float w2s[HID * OUT_CH];
    __shared__ float b2s[OUT_CH];
    for (int i = threadIdx.x; i < HID * OUT_CH; i += blockDim.x) w2s[i] = W2[i];
    for (int i = threadIdx.x; i < OUT_CH;       i += blockDim.x) b2s[i] = b2[i];
    __syncthreads();

    int t = blockIdx.x * blockDim.x + threadIdx.x;
    int nid = t >> 2;
    int c4  = t & 3;
    unsigned gmask = 0xFu << ((threadIdx.x & 31) & ~3);
    if (nid >= N_NODES) return;
    int beg = rowptr[nid];
    int end = rowptr[nid + 1];
    float4 m = gather_mean((const float4*)h, csr_src, beg, end, c4, gmask);

    // share the 16 mean channels across the 4-lane group
    float ma[16];
    #pragma unroll
    for (int sl = 0; sl < 4; sl++) {
        ma[sl * 4 + 0] = __shfl_sync(gmask, m.x, sl, 4);
        ma[sl * 4 + 1] = __shfl_sync(gmask, m.y, sl, 4);
        ma[sl * 4 + 2] = __shfl_sync(gmask, m.z, sl, 4);
        ma[sl * 4 + 3] = __shfl_sync(gmask, m.w, sl, 4);
    }

    // each lane computes logits j = c4 + 4*i
    float o[11];
    float lmax = -1e30f;
    int cnt = 0;
    for (int jj = c4; jj < OUT_CH; jj += 4, cnt++) {
        float v = b2s[jj];
        #pragma unroll
        for (int k = 0; k < HID; k++)
            v += ma[k] * w2s[k * OUT_CH + jj];
        o[cnt] = v;
        lmax = fmaxf(lmax, v);
    }
    lmax = fmaxf(lmax, __shfl_xor_sync(gmask, lmax, 1));
    lmax = fmaxf(lmax, __shfl_xor_sync(gmask, lmax, 2));
    float lsum = 0.f;
    for (int i = 0; i < cnt; i++) lsum += __expf(o[i] - lmax);
    lsum += __shfl_xor_sync(gmask, lsum, 1);
    lsum += __shfl_xor_sync(gmask, lsum, 2);
    float ls = __logf(lsum) + lmax;

    float* op = out + (size_t)nid * OUT_CH;
    int i = 0;
    for (int jj = c4; jj < OUT_CH; jj += 4, i++) op[jj] = o[i] - ls;
}

// ---------------------------------------------------------------------------
extern "C" void kernel_launch(void* const* d_in, const int* in_sizes, int n_in,
                              void* d_out, int out_size) {
    const float* x  = (const float*)d_in[0];
    const int*   ei = (const int*)  d_in[1];
    const float* W1 = (const float*)d_in[2];
    const float* b1 = (const float*)d_in[3];
    const float* W2 = (const float*)d_in[4];
    const float* b2 = (const float*)d_in[5];
    float* out = (float*)d_out;

    const int* src = ei;
    const int* dst = ei + N_EDGES;

    float *p_h1, *p_r;
    int *p_deg, *p_excl, *p_blksum, *p_rowptr, *p_cursor, *p_csr;
    cudaGetSymbolAddress((void**)&p_h1,     g_h1);
    cudaGetSymbolAddress((void**)&p_r,      g_r);
    cudaGetSymbolAddress((void**)&p_deg,    g_deg);
    cudaGetSymbolAddress((void**)&p_excl,   g_excl);
    cudaGetSymbolAddress((void**)&p_blksum, g_blksum);
    cudaGetSymbolAddress((void**)&p_rowptr, g_rowptr);
    cudaGetSymbolAddress((void**)&p_cursor, g_cursor);
    cudaGetSymbolAddress((void**)&p_csr,    g_csr);

    // Side stream + fork/join events (created on first call, which is the
    // uncaptured correctness run; reused identically during graph capture).
    static cudaStream_t s_csr = nullptr;
    static cudaEvent_t  ev_fork = nullptr, ev_join = nullptr;
    if (s_csr == nullptr) {
        cudaStreamCreateWithFlags(&s_csr, cudaStreamNonBlocking);
        cudaEventCreateWithFlags(&ev_fork, cudaEventDisableTiming);
        cudaEventCreateWithFlags(&ev_join, cudaEventDisableTiming);
    }

    // Fork: CSR chain on side stream, gemm on main stream — independent.
    cudaEventRecord(ev_fork, 0);
    cudaStreamWaitEvent(s_csr, ev_fork, 0);

    cudaMemsetAsync(p_deg, 0, sizeof(int) * N_NODES, s_csr);
    deg_kernel <<<(N_EDGES + 255) / 256, 256, 0, s_csr>>>(dst, p_deg);
    scan1_kernel<<<NB_SCAN, SCAN_BLK, 0, s_csr>>>(p_deg, p_excl, p_blksum);
    scan2_kernel<<<1, 128, 0, s_csr>>>(p_blksum);
    scan3_kernel<<<(N_NODES + 255) / 256, 256, 0, s_csr>>>(p_excl, p_blksum, p_rowptr, p_cursor);
    fill_kernel <<<(N_EDGES + 255) / 256, 256, 0, s_csr>>>(src, dst, p_cursor, p_csr);
    cudaEventRecord(ev_join, s_csr);

    // K1 on main stream, overlapped with CSR build
    gemm1_kernel<<<(N_NODES + M_TILE - 1) / M_TILE, 256>>>(x, W1, p_h1);

    // Join: gather1 needs both h1 and the CSR
    cudaStreamWaitEvent(0, ev_join, 0);

    gather1_kernel<<<(N_NODES * 4 + 255) / 256, 256>>>(p_h1, p_rowptr, p_csr, b1, p_r);
    gather2_out_kernel<<<(N_NODES * 4 + 255) / 256, 256>>>(p_r, p_rowptr, p_csr, W2, b2, out);
}